// round 3
// baseline (speedup 1.0000x reference)
#include <cuda_runtime.h>
#include <cuda_bf16.h>
#include <math.h>

// ---------------------------------------------------------------------------
// SwinV2 WindowAttention, fused. B=4096 windows, N=64 tokens, C=192, H=6, HD=32.
// One CTA per window. fp32 everywhere (round-1 baseline).
// ---------------------------------------------------------------------------

#define NWIN   4096
#define NTOK   64
#define CDIM   192
#define NHEAD  6
#define HDIM   32
#define NMASK  1024

// smem strides (floats)
#define XS   196     // row stride for x / q / v / o (192 + 4 pad, not mult of 32)
#define KTS  65      // kT stride: kt[d][n], d=0..191, n=0..63
#define SS   68      // score row stride

// smem layout offsets (floats)
#define OFF_X   0
#define OFF_Q   12544              // 64*196
#define OFF_V   25088
#define OFF_KT  37632
#define OFF_SW  50112              // union: w_tile (16*192=3072) / scores (64*68=4352)
#define OFF_QN  54464              // 64*6
#define OFF_KN  54848
#define OFF_SC  55232              // 6 + pad
#define SMEM_FLOATS 55240
#define SMEM_BYTES (SMEM_FLOATS * 4)

__device__ float g_bias[NHEAD * NTOK * NTOK];   // 16*sigmoid(cpb) bias, [h][p][q]

// ---------------------------------------------------------------------------
// Kernel 1: continuous position bias MLP -> g_bias
// ---------------------------------------------------------------------------
__global__ void bias_kernel(const float* __restrict__ fc1_w,   // [2,512]
                            const float* __restrict__ fc1_b,   // [512]
                            const float* __restrict__ fc2_w)   // [512,6]
{
    __shared__ float tb[225 * 6];
    int tid = threadIdx.x;

    if (tid < 225) {
        int i = tid / 15, j = tid % 15;
        // coords table: table[i][j][0] = rc[j], table[i][j][1] = rc[i]; rc=-7..7
        float v0 = (float)(j - 7) * (8.0f / 7.0f);
        float v1 = (float)(i - 7) * (8.0f / 7.0f);
        // sign(v)*log2(|v|+1)/log2(8)
        float s0 = (v0 > 0.f) ? 1.f : ((v0 < 0.f) ? -1.f : 0.f);
        float s1 = (v1 > 0.f) ? 1.f : ((v1 < 0.f) ? -1.f : 0.f);
        v0 = s0 * log2f(fabsf(v0) + 1.0f) * (1.0f / 3.0f);
        v1 = s1 * log2f(fabsf(v1) + 1.0f) * (1.0f / 3.0f);

        float acc[NHEAD];
#pragma unroll
        for (int h = 0; h < NHEAD; h++) acc[h] = 0.f;
        for (int u = 0; u < 512; u++) {
            float hv = fmaxf(v0 * fc1_w[u] + v1 * fc1_w[512 + u] + fc1_b[u], 0.f);
#pragma unroll
            for (int h = 0; h < NHEAD; h++) acc[h] += hv * fc2_w[u * NHEAD + h];
        }
#pragma unroll
        for (int h = 0; h < NHEAD; h++) tb[tid * NHEAD + h] = acc[h];
    }
    __syncthreads();

    for (int i = tid; i < NHEAD * NTOK * NTOK; i += blockDim.x) {
        int h = i >> 12;
        int pq = i & 4095;
        int p = pq >> 6, q = pq & 63;
        int idx = ((p >> 3) - (q >> 3) + 7) * 15 + ((p & 7) - (q & 7) + 7);
        float x = tb[idx * NHEAD + h];
        g_bias[i] = 16.0f / (1.0f + __expf(-x));
    }
}

// ---------------------------------------------------------------------------
// 64x192 @ 192x192 GEMM accumulate: thread (ty,tx) in 16x16 grid computes
// rows ty*4..+3, cols {tx*4 + seg*64 + j}.
// in_s: smem, row stride XS.  w_g: global [192][192] row-major.
// w_tile: smem [16][192] staging (OFF_SW region).
// ---------------------------------------------------------------------------
__device__ __forceinline__ void gemm192(const float* __restrict__ in_s,
                                        const float* __restrict__ w_g,
                                        float* __restrict__ w_tile,
                                        float acc[4][12],
                                        int ty, int tx, int tid)
{
#pragma unroll
    for (int r = 0; r < 4; r++)
#pragma unroll
        for (int c = 0; c < 12; c++) acc[r][c] = 0.f;

    for (int kc = 0; kc < 12; kc++) {
        // stage 16x192 weight rows
        const float4* wg4 = (const float4*)(w_g + kc * 16 * CDIM);
        float4* wt4 = (float4*)w_tile;
#pragma unroll
        for (int i = 0; i < 3; i++) wt4[tid + i * 256] = wg4[tid + i * 256];
        __syncthreads();

#pragma unroll
        for (int kk = 0; kk < 16; kk++) {
            float a[4];
#pragma unroll
            for (int r = 0; r < 4; r++)
                a[r] = in_s[(ty * 4 + r) * XS + kc * 16 + kk];
#pragma unroll
            for (int seg = 0; seg < 3; seg++) {
                float4 wv = *(const float4*)&w_tile[kk * CDIM + seg * 64 + tx * 4];
#pragma unroll
                for (int r = 0; r < 4; r++) {
                    acc[r][seg * 4 + 0] = fmaf(a[r], wv.x, acc[r][seg * 4 + 0]);
                    acc[r][seg * 4 + 1] = fmaf(a[r], wv.y, acc[r][seg * 4 + 1]);
                    acc[r][seg * 4 + 2] = fmaf(a[r], wv.z, acc[r][seg * 4 + 2]);
                    acc[r][seg * 4 + 3] = fmaf(a[r], wv.w, acc[r][seg * 4 + 3]);
                }
            }
        }
        __syncthreads();
    }
}

// ---------------------------------------------------------------------------
// Main fused kernel: one block per window.
// ---------------------------------------------------------------------------
__global__ void __launch_bounds__(256, 1)
win_attn_kernel(const float* __restrict__ x_g,      // [4096,64,192]
                const float* __restrict__ mask_g,   // [1024,64,64]
                const float* __restrict__ logit_scale, // [6]
                const float* __restrict__ q_w, const float* __restrict__ q_b,
                const float* __restrict__ k_w,
                const float* __restrict__ v_w, const float* __restrict__ v_b,
                const float* __restrict__ p_w, const float* __restrict__ p_b,
                float* __restrict__ out_g)          // [4096,64,192]
{
    extern __shared__ float sm[];
    float* xs  = sm + OFF_X;    // x, later o
    float* qs  = sm + OFF_Q;
    float* vs  = sm + OFF_V;
    float* kts = sm + OFF_KT;
    float* sw  = sm + OFF_SW;   // w_tile / scores
    float* qn  = sm + OFF_QN;
    float* kn  = sm + OFF_KN;
    float* sc  = sm + OFF_SC;

    const int tid = threadIdx.x;
    const int b   = blockIdx.x;
    const int ty  = tid >> 4, tx = tid & 15;

    // ---- load x [64][192] ----
    {
        const float4* xg4 = (const float4*)(x_g + (size_t)b * NTOK * CDIM);
#pragma unroll
        for (int i = 0; i < 12; i++) {
            int e = tid + i * 256;           // 3072 float4 total
            int n = e / 48, c4 = e % 48;
            *(float4*)&xs[n * XS + c4 * 4] = xg4[e];
        }
    }
    if (tid < NHEAD)
        sc[tid] = __expf(fminf(logit_scale[tid], 4.60517019f)); // ln(100)
    __syncthreads();

    float acc[4][12];

    // ---- Q = x @ q_w + q_b ----
    gemm192(xs, q_w, sw, acc, ty, tx, tid);
#pragma unroll
    for (int seg = 0; seg < 3; seg++) {
        int c0 = seg * 64 + tx * 4;
        float4 bb = *(const float4*)&q_b[c0];
#pragma unroll
        for (int r = 0; r < 4; r++) {
            float4 v;
            v.x = acc[r][seg * 4 + 0] + bb.x;
            v.y = acc[r][seg * 4 + 1] + bb.y;
            v.z = acc[r][seg * 4 + 2] + bb.z;
            v.w = acc[r][seg * 4 + 3] + bb.w;
            *(float4*)&qs[(ty * 4 + r) * XS + c0] = v;
        }
    }

    // ---- K = x @ k_w  (stored transposed: kt[d][n]) ----
    gemm192(xs, k_w, sw, acc, ty, tx, tid);
#pragma unroll
    for (int seg = 0; seg < 3; seg++) {
        int c0 = seg * 64 + tx * 4;
#pragma unroll
        for (int r = 0; r < 4; r++) {
            int n = ty * 4 + r;
#pragma unroll
            for (int j = 0; j < 4; j++)
                kts[(c0 + j) * KTS + n] = acc[r][seg * 4 + j];
        }
    }

    // ---- V = x @ v_w + v_b ----
    gemm192(xs, v_w, sw, acc, ty, tx, tid);
#pragma unroll
    for (int seg = 0; seg < 3; seg++) {
        int c0 = seg * 64 + tx * 4;
        float4 bb = *(const float4*)&v_b[c0];
#pragma unroll
        for (int r = 0; r < 4; r++) {
            float4 v;
            v.x = acc[r][seg * 4 + 0] + bb.x;
            v.y = acc[r][seg * 4 + 1] + bb.y;
            v.z = acc[r][seg * 4 + 2] + bb.z;
            v.w = acc[r][seg * 4 + 3] + bb.w;
            *(float4*)&vs[(ty * 4 + r) * XS + c0] = v;
        }
    }
    __syncthreads();

    // ---- per-(n,h) inverse L2 norms (scale folded into qn) ----
    for (int p = tid; p < NTOK * NHEAD; p += 256) {
        int n = p / NHEAD, h = p % NHEAD;
        float s0 = 0.f, s1 = 0.f;
#pragma unroll
        for (int d = 0; d < HDIM; d++) {
            float qv = qs[n * XS + h * HDIM + d];
            float kv = kts[(h * HDIM + d) * KTS + n];
            s0 += qv * qv;
            s1 += kv * kv;
        }
        qn[p] = sc[h] * rsqrtf(s0);
        kn[p] = rsqrtf(s1);
    }
    __syncthreads();

    const float* mrow = mask_g + (size_t)(b & (NMASK - 1)) * NTOK * NTOK;
    const int warp = tid >> 5, lane = tid & 31;
    const int ty2 = tid >> 3, tx2 = tid & 7;

    // ---- per-head attention ----
    for (int h = 0; h < NHEAD; h++) {
        // scores: s[p][q] = (q_row . k_row) * qn * kn + bias + mask
        float sa[4][4];
#pragma unroll
        for (int r = 0; r < 4; r++)
#pragma unroll
            for (int c = 0; c < 4; c++) sa[r][c] = 0.f;

#pragma unroll
        for (int kk = 0; kk < HDIM; kk++) {
            float a[4], bqv[4];
#pragma unroll
            for (int r = 0; r < 4; r++)
                a[r] = qs[(ty * 4 + r) * XS + h * HDIM + kk];
#pragma unroll
            for (int c = 0; c < 4; c++)
                bqv[c] = kts[(h * HDIM + kk) * KTS + tx * 4 + c];
#pragma unroll
            for (int r = 0; r < 4; r++)
#pragma unroll
                for (int c = 0; c < 4; c++)
                    sa[r][c] = fmaf(a[r], bqv[c], sa[r][c]);
        }
#pragma unroll
        for (int r = 0; r < 4; r++) {
            int p = ty * 4 + r;
            float4 bi = *(const float4*)&g_bias[h * 4096 + p * 64 + tx * 4];
            float4 mk = *(const float4*)&mrow[p * 64 + tx * 4];
            float qnv = qn[p * NHEAD + h];
            float v0 = sa[r][0] * qnv * kn[(tx * 4 + 0) * NHEAD + h] + bi.x + mk.x;
            float v1 = sa[r][1] * qnv * kn[(tx * 4 + 1) * NHEAD + h] + bi.y + mk.y;
            float v2 = sa[r][2] * qnv * kn[(tx * 4 + 2) * NHEAD + h] + bi.z + mk.z;
            float v3 = sa[r][3] * qnv * kn[(tx * 4 + 3) * NHEAD + h] + bi.w + mk.w;
            float4 v = {v0, v1, v2, v3};
            *(float4*)&sw[p * SS + tx * 4] = v;
        }
        __syncthreads();

        // softmax: warp w handles rows w*8..w*8+7
#pragma unroll
        for (int rr = 0; rr < 8; rr++) {
            int p = warp * 8 + rr;
            float v0 = sw[p * SS + lane];
            float v1 = sw[p * SS + 32 + lane];
            float m = fmaxf(v0, v1);
#pragma unroll
            for (int off = 16; off > 0; off >>= 1)
                m = fmaxf(m, __shfl_xor_sync(0xffffffffu, m, off));
            float e0 = __expf(v0 - m), e1 = __expf(v1 - m);
            float s = e0 + e1;
#pragma unroll
            for (int off = 16; off > 0; off >>= 1)
                s += __shfl_xor_sync(0xffffffffu, s, off);
            float inv = 1.0f / s;
            sw[p * SS + lane]      = e0 * inv;
            sw[p * SS + 32 + lane] = e1 * inv;
        }
        __syncthreads();

        // o[p][h*32+d] = s @ v : thread (ty2, tx2) -> rows ty2*2..+1, cols tx2*4..+3
        float4 o0 = {0.f, 0.f, 0.f, 0.f}, o1 = {0.f, 0.f, 0.f, 0.f};
#pragma unroll 4
        for (int q = 0; q < NTOK; q++) {
            float4 vv = *(const float4*)&vs[q * XS + h * HDIM + tx2 * 4];
            float a0 = sw[(ty2 * 2 + 0) * SS + q];
            float a1 = sw[(ty2 * 2 + 1) * SS + q];
            o0.x = fmaf(a0, vv.x, o0.x); o0.y = fmaf(a0, vv.y, o0.y);
            o0.z = fmaf(a0, vv.z, o0.z); o0.w = fmaf(a0, vv.w, o0.w);
            o1.x = fmaf(a1, vv.x, o1.x); o1.y = fmaf(a1, vv.y, o1.y);
            o1.z = fmaf(a1, vv.z, o1.z); o1.w = fmaf(a1, vv.w, o1.w);
        }
        *(float4*)&xs[(ty2 * 2 + 0) * XS + h * HDIM + tx2 * 4] = o0;
        *(float4*)&xs[(ty2 * 2 + 1) * XS + h * HDIM + tx2 * 4] = o1;
        __syncthreads();
    }

    // ---- out = o @ proj_w + proj_b (o lives in xs) ----
    gemm192(xs, p_w, sw, acc, ty, tx, tid);
    {
        float* og = out_g + (size_t)b * NTOK * CDIM;
#pragma unroll
        for (int seg = 0; seg < 3; seg++) {
            int c0 = seg * 64 + tx * 4;
            float4 bb = *(const float4*)&p_b[c0];
#pragma unroll
            for (int r = 0; r < 4; r++) {
                float4 v;
                v.x = acc[r][seg * 4 + 0] + bb.x;
                v.y = acc[r][seg * 4 + 1] + bb.y;
                v.z = acc[r][seg * 4 + 2] + bb.z;
                v.w = acc[r][seg * 4 + 3] + bb.w;
                *(float4*)&og[(ty * 4 + r) * CDIM + c0] = v;
            }
        }
    }
}

// ---------------------------------------------------------------------------
extern "C" void kernel_launch(void* const* d_in, const int* in_sizes, int n_in,
                              void* d_out, int out_size)
{
    const float* hs   = (const float*)d_in[0];
    const float* mask = (const float*)d_in[1];
    const float* lsc  = (const float*)d_in[2];
    const float* fc1w = (const float*)d_in[3];
    const float* fc1b = (const float*)d_in[4];
    const float* fc2w = (const float*)d_in[5];
    const float* qw   = (const float*)d_in[6];
    const float* qb   = (const float*)d_in[7];
    const float* kw   = (const float*)d_in[8];
    const float* vw   = (const float*)d_in[9];
    const float* vb   = (const float*)d_in[10];
    const float* pw   = (const float*)d_in[11];
    const float* pb   = (const float*)d_in[12];
    float* out = (float*)d_out;

    bias_kernel<<<1, 256>>>(fc1w, fc1b, fc2w);

    cudaFuncSetAttribute(win_attn_kernel,
                         cudaFuncAttributeMaxDynamicSharedMemorySize, SMEM_BYTES);
    win_attn_kernel<<<NWIN, 256, SMEM_BYTES>>>(hs, mask, lsc,
                                               qw, qb, kw, vw, vb, pw, pb, out);
}

// round 5
// speedup vs baseline: 2.9240x; 2.9240x over previous
#include <cuda_runtime.h>
#include <cuda_fp16.h>
#include <stdint.h>
#include <math.h>

// ---------------------------------------------------------------------------
// SwinV2 WindowAttention via HMMA (mma.sync.m16n8k16 fp16->fp32).
// 4096 windows, N=64 tok, C=192, H=6, HD=32. 1 window/CTA, 256 threads.
// ---------------------------------------------------------------------------

#define NWIN 4096
#define STR  200          // row stride (halves) for X/Q/K/O/W tiles: 400B, conflict-free
#define VSTR 72           // row stride (halves) for vt/P: 144B, conflict-free

// smem byte offsets
#define OFF_XS 0          // X fp16 [64][STR], later O
#define OFF_WT 25600      // weight tile fp16 [192][STR]
#define OFF_QH 102400     // Qhat fp16 [64][STR]
#define OFF_KH 128000     // Khat fp16 [64][STR]
#define OFF_VT 153600     // Vt fp16 [192][VSTR]
#define OFF_SS 181248     // scores f32 [64][72]
#define OFF_P  199680     // P fp16 [64][VSTR]
#define OFF_SC 208896     // 6 floats
#define SMEM_BYTES 208960

__device__ __align__(16) __half g_wt[4 * 192 * STR];   // fp16 Wt[n][k] images (q,k,v,proj)
__device__ float g_bias[6 * 64 * 64];

// ---------------- helpers ----------------
__device__ __forceinline__ uint32_t smem_u32(const void* p) {
    uint32_t a;
    asm("{ .reg .u64 t; cvta.to.shared.u64 t, %1; cvt.u32.u64 %0, t; }" : "=r"(a) : "l"(p));
    return a;
}
__device__ __forceinline__ void ldsm4(uint32_t addr, uint32_t r[4]) {
    asm volatile("ldmatrix.sync.aligned.m8n8.x4.shared.b16 {%0,%1,%2,%3}, [%4];"
        : "=r"(r[0]), "=r"(r[1]), "=r"(r[2]), "=r"(r[3]) : "r"(addr));
}
__device__ __forceinline__ void ldsm2(uint32_t addr, uint32_t r[2]) {
    asm volatile("ldmatrix.sync.aligned.m8n8.x2.shared.b16 {%0,%1}, [%2];"
        : "=r"(r[0]), "=r"(r[1]) : "r"(addr));
}
__device__ __forceinline__ void mma16816(float c[4], const uint32_t a[4], uint32_t b0, uint32_t b1) {
    asm volatile("mma.sync.aligned.m16n8k16.row.col.f32.f16.f16.f32 "
        "{%0,%1,%2,%3}, {%4,%5,%6,%7}, {%8,%9}, {%0,%1,%2,%3};"
        : "+f"(c[0]), "+f"(c[1]), "+f"(c[2]), "+f"(c[3])
        : "r"(a[0]), "r"(a[1]), "r"(a[2]), "r"(a[3]), "r"(b0), "r"(b1));
}
__device__ __forceinline__ uint32_t pack2(float a, float b) {
    __half2 h = __floats2half2_rn(a, b);
    return *reinterpret_cast<uint32_t*>(&h);
}

// ---------------- prologue kernels ----------------
__global__ void prep_w_kernel(const float* __restrict__ qw, const float* __restrict__ kw,
                              const float* __restrict__ vw, const float* __restrict__ pw)
{
    int i = blockIdx.x * 256 + threadIdx.x;           // 576*256 = 147456 = 4*192*192
    int w = i / 36864, r = i % 36864;
    int k = r / 192, n = r % 192;
    const float* W = (w == 0) ? qw : (w == 1) ? kw : (w == 2) ? vw : pw;
    g_wt[w * 192 * STR + n * STR + k] = __float2half(W[k * 192 + n]);
}

__global__ void bias_kernel(const float* __restrict__ fc1_w, const float* __restrict__ fc1_b,
                            const float* __restrict__ fc2_w)
{
    __shared__ float tb[225 * 6];
    int tid = threadIdx.x;
    if (tid < 225) {
        int i = tid / 15, j = tid % 15;
        float v0 = (float)(j - 7) * (8.0f / 7.0f);
        float v1 = (float)(i - 7) * (8.0f / 7.0f);
        float s0 = (v0 > 0.f) ? 1.f : ((v0 < 0.f) ? -1.f : 0.f);
        float s1 = (v1 > 0.f) ? 1.f : ((v1 < 0.f) ? -1.f : 0.f);
        v0 = s0 * log2f(fabsf(v0) + 1.0f) * (1.0f / 3.0f);
        v1 = s1 * log2f(fabsf(v1) + 1.0f) * (1.0f / 3.0f);
        float acc[6];
#pragma unroll
        for (int h = 0; h < 6; h++) acc[h] = 0.f;
        for (int u = 0; u < 512; u++) {
            float hv = fmaxf(v0 * fc1_w[u] + v1 * fc1_w[512 + u] + fc1_b[u], 0.f);
#pragma unroll
            for (int h = 0; h < 6; h++) acc[h] += hv * fc2_w[u * 6 + h];
        }
#pragma unroll
        for (int h = 0; h < 6; h++) tb[tid * 6 + h] = acc[h];
    }
    __syncthreads();
    for (int i = tid; i < 6 * 64 * 64; i += blockDim.x) {
        int h = i >> 12, pq = i & 4095, p = pq >> 6, q = pq & 63;
        int idx = ((p >> 3) - (q >> 3) + 7) * 15 + ((p & 7) - (q & 7) + 7);
        g_bias[i] = 16.0f / (1.0f + __expf(-tb[idx * 6 + h]));
    }
}

// ---------------- main kernel ----------------
__device__ __forceinline__ void stage_w(char* smc, int widx, int tid) {
    const float4* s = (const float4*)(g_wt + widx * 192 * STR);
    float4* d = (float4*)(smc + OFF_WT);
    for (int i = tid; i < 192 * STR * 2 / 16; i += 256) d[i] = s[i];
}

// M=64, N=192, K=192: warp w -> N cols [w*24, w*24+24)
__device__ __forceinline__ void gemm192(uint32_t a_su, uint32_t w_su, int warp, int lane,
                                        float c[12][4])
{
#pragma unroll
    for (int i = 0; i < 12; i++) { c[i][0] = c[i][1] = c[i][2] = c[i][3] = 0.f; }
    const int wn = warp * 24;
    const uint32_t arow = (lane & 15), ak8 = (lane >> 4) * 8;
    const uint32_t brow = (lane & 7),  bk8 = ((lane >> 3) & 1) * 8;
#pragma unroll
    for (int ks = 0; ks < 12; ks++) {
        uint32_t A[4][4];
#pragma unroll
        for (int mt = 0; mt < 4; mt++)
            ldsm4(a_su + ((mt * 16 + arow) * STR + ks * 16 + ak8) * 2, A[mt]);
#pragma unroll
        for (int nt = 0; nt < 3; nt++) {
            uint32_t B[2];
            ldsm2(w_su + ((wn + nt * 8 + brow) * STR + ks * 16 + bk8) * 2, B);
#pragma unroll
            for (int mt = 0; mt < 4; mt++) mma16816(c[mt * 3 + nt], A[mt], B[0], B[1]);
        }
    }
}

// L2-normalize rows of a [64][192] fp16 tile per (token, head) slice of 32
__device__ __forceinline__ void norm_rows(char* smc, uint32_t off, const float* scs,
                                          bool useScale, int tid)
{
    for (int p = tid; p < 384; p += 256) {
        int h = p >> 6, m = p & 63;
        __half2* ptr = (__half2*)(smc + off + (m * STR + h * 32) * 2);
        float s = 0.f;
        __half2 vv[16];
#pragma unroll
        for (int j = 0; j < 16; j++) {
            vv[j] = ptr[j];
            float2 f = __half22float2(vv[j]);
            s += f.x * f.x + f.y * f.y;
        }
        float scl = rsqrtf(s) * (useScale ? scs[h] : 1.f);
        __half2 hs = __floats2half2_rn(scl, scl);
#pragma unroll
        for (int j = 0; j < 16; j++) ptr[j] = __hmul2(vv[j], hs);
    }
}

__global__ void __launch_bounds__(256, 1)
win_attn_hmma(const float* __restrict__ x_g, const float* __restrict__ mask_g,
              const float* __restrict__ lsc,
              const float* __restrict__ qb, const float* __restrict__ vb,
              const float* __restrict__ pb, float* __restrict__ out_g)
{
    extern __shared__ char smc[];
    const uint32_t su = smem_u32(smc);
    const int tid = threadIdx.x, warp = tid >> 5, lane = tid & 31;
    const int blk = blockIdx.x;
    const int r = lane >> 2, cc = (lane & 3) * 2;
    float* scs = (float*)(smc + OFF_SC);
    float c[12][4];

    // ---- load X -> fp16 smem; stage Wq ----
    {
        const float4* xg = (const float4*)(x_g + (size_t)blk * 64 * 192);
#pragma unroll
        for (int i = 0; i < 12; i++) {
            int e = tid + i * 256;               // 3072 float4
            int row = e / 48, c4 = e % 48;
            float4 v = xg[e];
            char* p = smc + OFF_XS + (row * STR + c4 * 4) * 2;
            *(uint32_t*)(p)     = pack2(v.x, v.y);
            *(uint32_t*)(p + 4) = pack2(v.z, v.w);
        }
    }
    stage_w(smc, 0, tid);
    if (tid < 6) scs[tid] = __expf(fminf(lsc[tid], 4.60517019f));
    __syncthreads();

    // ---- Q ----
    gemm192(su + OFF_XS, su + OFF_WT, warp, lane, c);
#pragma unroll
    for (int mt = 0; mt < 4; mt++)
#pragma unroll
        for (int nt = 0; nt < 3; nt++) {
            int n = warp * 24 + nt * 8 + cc, m = mt * 16 + r;
            float b0 = qb[n], b1 = qb[n + 1];
            *(uint32_t*)(smc + OFF_QH + (m * STR + n) * 2)       = pack2(c[mt*3+nt][0] + b0, c[mt*3+nt][1] + b1);
            *(uint32_t*)(smc + OFF_QH + ((m + 8) * STR + n) * 2) = pack2(c[mt*3+nt][2] + b0, c[mt*3+nt][3] + b1);
        }
    __syncthreads();
    norm_rows(smc, OFF_QH, scs, true, tid);
    stage_w(smc, 1, tid);
    __syncthreads();

    // ---- K ----
    gemm192(su + OFF_XS, su + OFF_WT, warp, lane, c);
#pragma unroll
    for (int mt = 0; mt < 4; mt++)
#pragma unroll
        for (int nt = 0; nt < 3; nt++) {
            int n = warp * 24 + nt * 8 + cc, m = mt * 16 + r;
            *(uint32_t*)(smc + OFF_KH + (m * STR + n) * 2)       = pack2(c[mt*3+nt][0], c[mt*3+nt][1]);
            *(uint32_t*)(smc + OFF_KH + ((m + 8) * STR + n) * 2) = pack2(c[mt*3+nt][2], c[mt*3+nt][3]);
        }
    __syncthreads();
    norm_rows(smc, OFF_KH, scs, false, tid);
    stage_w(smc, 2, tid);
    __syncthreads();

    // ---- V (written transposed: vt[dim][token]) ----
    gemm192(su + OFF_XS, su + OFF_WT, warp, lane, c);
#pragma unroll
    for (int mt = 0; mt < 4; mt++)
#pragma unroll
        for (int nt = 0; nt < 3; nt++) {
            int n = warp * 24 + nt * 8 + cc, m = mt * 16 + r;
            float b0 = vb[n], b1 = vb[n + 1];
            *(__half*)(smc + OFF_VT + (n * VSTR + m) * 2)           = __float2half(c[mt*3+nt][0] + b0);
            *(__half*)(smc + OFF_VT + ((n + 1) * VSTR + m) * 2)     = __float2half(c[mt*3+nt][1] + b1);
            *(__half*)(smc + OFF_VT + (n * VSTR + m + 8) * 2)       = __float2half(c[mt*3+nt][2] + b0);
            *(__half*)(smc + OFF_VT + ((n + 1) * VSTR + m + 8) * 2) = __float2half(c[mt*3+nt][3] + b1);
        }
    __syncthreads();

    // ---- attention, per head ----
    const uint32_t arow = (lane & 15), ak8 = (lane >> 4) * 8;
    const uint32_t brow = (lane & 7),  bk8 = ((lane >> 3) & 1) * 8;
    const int srow = tid >> 2, q4 = tid & 3;
    const float* bi_base = g_bias + srow * 64 + q4 * 16;
    const float* mk = mask_g + (size_t)(blk & 1023) * 4096 + srow * 64 + q4 * 16;

    for (int h = 0; h < 6; h++) {
        // S = Qhat @ Khat^T : M=64, N=64 (warp: 8 cols), K=32
        float cs[4][4];
#pragma unroll
        for (int i = 0; i < 4; i++) { cs[i][0] = cs[i][1] = cs[i][2] = cs[i][3] = 0.f; }
#pragma unroll
        for (int ks = 0; ks < 2; ks++) {
            uint32_t A[4][4], B[2];
#pragma unroll
            for (int mt = 0; mt < 4; mt++)
                ldsm4(su + OFF_QH + ((mt * 16 + arow) * STR + h * 32 + ks * 16 + ak8) * 2, A[mt]);
            ldsm2(su + OFF_KH + ((warp * 8 + brow) * STR + h * 32 + ks * 16 + bk8) * 2, B);
#pragma unroll
            for (int mt = 0; mt < 4; mt++) mma16816(cs[mt], A[mt], B[0], B[1]);
        }
#pragma unroll
        for (int mt = 0; mt < 4; mt++) {
            int m = mt * 16 + r, n = warp * 8 + cc;
            *(float2*)(smc + OFF_SS + (m * 72 + n) * 4)       = make_float2(cs[mt][0], cs[mt][1]);
            *(float2*)(smc + OFF_SS + ((m + 8) * 72 + n) * 4) = make_float2(cs[mt][2], cs[mt][3]);
        }
        __syncthreads();

        // softmax: quad per row, 16 cols per thread
        {
            const float* ssr = (const float*)(smc + OFF_SS) + srow * 72 + q4 * 16;
            const float* bi = bi_base + h * 4096;
            float l[16];
#pragma unroll
            for (int j = 0; j < 16; j += 4) {
                float4 s4 = *(const float4*)(ssr + j);
                float4 b4 = *(const float4*)(bi + j);
                float4 m4 = *(const float4*)(mk + j);
                l[j + 0] = s4.x + b4.x + m4.x;
                l[j + 1] = s4.y + b4.y + m4.y;
                l[j + 2] = s4.z + b4.z + m4.z;
                l[j + 3] = s4.w + b4.w + m4.w;
            }
            float mx = l[0];
#pragma unroll
            for (int j = 1; j < 16; j++) mx = fmaxf(mx, l[j]);
            mx = fmaxf(mx, __shfl_xor_sync(0xffffffffu, mx, 1));
            mx = fmaxf(mx, __shfl_xor_sync(0xffffffffu, mx, 2));
            float sum = 0.f;
#pragma unroll
            for (int j = 0; j < 16; j++) { l[j] = __expf(l[j] - mx); sum += l[j]; }
            sum += __shfl_xor_sync(0xffffffffu, sum, 1);
            sum += __shfl_xor_sync(0xffffffffu, sum, 2);
            float inv = 1.0f / sum;
            uint32_t* pr = (uint32_t*)(smc + OFF_P + (srow * VSTR + q4 * 16) * 2);
#pragma unroll
            for (int j = 0; j < 8; j++) pr[j] = pack2(l[2 * j] * inv, l[2 * j + 1] * inv);
        }
        __syncthreads();

        // O_h = P @ Vt_h : M=64, N=32, K=64. warp grid 2(M) x 4(N)
        {
            int mw = warp >> 2, nw = warp & 3;
            float co[2][4];
            co[0][0]=co[0][1]=co[0][2]=co[0][3]=0.f;
            co[1][0]=co[1][1]=co[1][2]=co[1][3]=0.f;
#pragma unroll
            for (int ks = 0; ks < 4; ks++) {
                uint32_t A[2][4], B[2];
#pragma unroll
                for (int mt = 0; mt < 2; mt++)
                    ldsm4(su + OFF_P + (((mw * 2 + mt) * 16 + arow) * VSTR + ks * 16 + ak8) * 2, A[mt]);
                ldsm2(su + OFF_VT + ((h * 32 + nw * 8 + brow) * VSTR + ks * 16 + bk8) * 2, B);
#pragma unroll
                for (int mt = 0; mt < 2; mt++) mma16816(co[mt], A[mt], B[0], B[1]);
            }
#pragma unroll
            for (int mt = 0; mt < 2; mt++) {
                int m = mw * 32 + mt * 16 + r, n = h * 32 + nw * 8 + cc;
                *(uint32_t*)(smc + OFF_XS + (m * STR + n) * 2)       = pack2(co[mt][0], co[mt][1]);
                *(uint32_t*)(smc + OFF_XS + ((m + 8) * STR + n) * 2) = pack2(co[mt][2], co[mt][3]);
            }
        }
        __syncthreads();
    }

    // ---- proj ----
    stage_w(smc, 3, tid);
    __syncthreads();
    gemm192(su + OFF_XS, su + OFF_WT, warp, lane, c);
    {
        float* og = out_g + (size_t)blk * 64 * 192;
#pragma unroll
        for (int mt = 0; mt < 4; mt++)
#pragma unroll
            for (int nt = 0; nt < 3; nt++) {
                int n = warp * 24 + nt * 8 + cc, m = mt * 16 + r;
                float b0 = pb[n], b1 = pb[n + 1];
                *(float2*)(og + m * 192 + n)       = make_float2(c[mt*3+nt][0] + b0, c[mt*3+nt][1] + b1);
                *(float2*)(og + (m + 8) * 192 + n) = make_float2(c[mt*3+nt][2] + b0, c[mt*3+nt][3] + b1);
            }
    }
}

// ---------------------------------------------------------------------------
extern "C" void kernel_launch(void* const* d_in, const int* in_sizes, int n_in,
                              void* d_out, int out_size)
{
    const float* hs   = (const float*)d_in[0];
    const float* mask = (const float*)d_in[1];
    const float* lsc  = (const float*)d_in[2];
    const float* fc1w = (const float*)d_in[3];
    const float* fc1b = (const float*)d_in[4];
    const float* fc2w = (const float*)d_in[5];
    const float* qw   = (const float*)d_in[6];
    const float* qb   = (const float*)d_in[7];
    const float* kw   = (const float*)d_in[8];
    const float* vw   = (const float*)d_in[9];
    const float* vb   = (const float*)d_in[10];
    const float* pw   = (const float*)d_in[11];
    const float* pb   = (const float*)d_in[12];
    float* out = (float*)d_out;

    prep_w_kernel<<<576, 256>>>(qw, kw, vw, pw);
    bias_kernel<<<1, 256>>>(fc1w, fc1b, fc2w);

    cudaFuncSetAttribute(win_attn_hmma, cudaFuncAttributeMaxDynamicSharedMemorySize, SMEM_BYTES);
    win_attn_hmma<<<NWIN, 256, SMEM_BYTES>>>(hs, mask, lsc, qb, vb, pb, out);
}